// round 17
// baseline (speedup 1.0000x reference)
#include <cuda_runtime.h>
#include <cuda_fp16.h>
#include <cstdint>
#include <cstddef>
#include <math.h>

// ---------------- constants ----------------
#define B_      256
#define T_      1024
#define DM      256
#define NH      16
#define DH      16
#define CCH     64
#define NCHUNK  16
#define MBT     (B_*T_)

#define OUT1_N  (MBT*DM)
#define KV_N    (B_*NH*DH*DH)
#define PG_N    (256*512)

// ---------------- scratch ----------------
__device__ float g_q[(size_t)OUT1_N];
__device__ float g_k[(size_t)OUT1_N];
__device__ float g_v[(size_t)OUT1_N];
__device__ float g_gp[(size_t)16*4096*256];
__device__ float g_temp8[16*8*512];
__device__ float g_wa[16*4096];
__device__ float g_pg8a[8*512];
__device__ float g_pg8b[8*512];
__device__ float g_giall[16*8*1536];
__device__ float g_rpart[4*16*128*256];
__device__ float g_tpart[8*128*512];
__device__ float4 g_xt[1024*128];

// fp16 buffers
__device__ __half g_reth[(size_t)OUT1_N], g_retl[(size_t)OUT1_N];
__device__ __half g_tmph[(size_t)OUT1_N];
__device__ __half g_wqkvh[768*256], g_wqkvl[768*256];
__device__ __half g_wgh[256*256];
__device__ __half g_wph[256*256];
__device__ __half g_wgph[256*1024], g_wgpl[256*1024];
__device__ __half g_zh[(size_t)16*8*16*4096], g_zl[(size_t)16*8*16*4096];
__device__ __half g_rh[16*8*4096], g_rl[16*8*4096];
__device__ __half g_t8h[128*512], g_t8l[128*512];
__device__ __half g_wgath[(size_t)16*256*4096], g_wgatl[(size_t)16*256*4096];
__device__ __half g_wglh[512*4096], g_wgll[512*4096];
__device__ __half g_wihh[1536*512], g_wihl[1536*512];

// ---------------- helpers ----------------
__device__ __forceinline__ uint32_t smem_u32(const void* p) {
    uint32_t a;
    asm("{ .reg .u64 t; cvta.to.shared.u64 t, %1; cvt.u32.u64 %0, t; }" : "=r"(a) : "l"(p));
    return a;
}
__device__ __forceinline__ void cp16(uint32_t s, const void* g) {
    asm volatile("cp.async.ca.shared.global [%0], [%1], 16;" :: "r"(s), "l"(g));
}
__device__ __forceinline__ void mma_f16(float* d, const uint32_t* a, const uint32_t* b)
{
    asm volatile(
        "mma.sync.aligned.m16n8k16.row.col.f32.f16.f16.f32 "
        "{%0,%1,%2,%3}, {%4,%5,%6,%7}, {%8,%9}, {%0,%1,%2,%3};"
        : "+f"(d[0]), "+f"(d[1]), "+f"(d[2]), "+f"(d[3])
        : "r"(a[0]), "r"(a[1]), "r"(a[2]), "r"(a[3]), "r"(b[0]), "r"(b[1]));
}
__device__ __forceinline__ void ldsm4(uint32_t& r0, uint32_t& r1, uint32_t& r2,
                                      uint32_t& r3, uint32_t a)
{
    asm volatile("ldmatrix.sync.aligned.m8n8.x4.shared.b16 {%0,%1,%2,%3}, [%4];"
        : "=r"(r0), "=r"(r1), "=r"(r2), "=r"(r3) : "r"(a));
}

// ---------------- fp32 -> fp16 hi/lo split ----------------
__global__ void split_hl_h(const float* __restrict__ x, __half* __restrict__ hi,
                           __half* __restrict__ lo, size_t n)
{
    size_t i = ((size_t)blockIdx.x*256 + threadIdx.x)*4;
    if (i >= n) return;
    float4 v = *(const float4*)(x + i);
    __half2 h01 = __floats2half2_rn(v.x, v.y);
    __half2 h23 = __floats2half2_rn(v.z, v.w);
    float2 f01 = __half22float2(h01);
    float2 f23 = __half22float2(h23);
    __half2 l01 = __floats2half2_rn(v.x - f01.x, v.y - f01.y);
    __half2 l23 = __floats2half2_rn(v.z - f23.x, v.w - f23.y);
    ((__half2*)(hi + i))[0] = h01;
    ((__half2*)(hi + i))[1] = h23;
    ((__half2*)(lo + i))[0] = l01;
    ((__half2*)(lo + i))[1] = l23;
}

// hi-only conversion, two tensors in one launch
__global__ void conv2_h(const float* __restrict__ x0, __half* __restrict__ h0,
                        const float* __restrict__ x1, __half* __restrict__ h1)
{
    int bid = blockIdx.x;
    const float* x = (bid < 64) ? x0 : x1;
    __half* h = (bid < 64) ? h0 : h1;
    int idx = (((bid < 64) ? bid : bid - 64)*256 + threadIdx.x)*4;
    float4 v = *(const float4*)(x + idx);
    ((__half2*)(h + idx))[0] = __floats2half2_rn(v.x, v.y);
    ((__half2*)(h + idx))[1] = __floats2half2_rn(v.z, v.w);
}

// transpose + hi/lo split of W_gat
__global__ void tsplit_wgat(const float* __restrict__ in, __half* __restrict__ oh,
                            __half* __restrict__ ol)
{
    __shared__ float tile[32][33];
    int h2 = blockIdx.z;
    int f0 = blockIdx.x*32, o0 = blockIdx.y*32;
    int tx = threadIdx.x, ty = threadIdx.y;
    const float* src = in + (size_t)h2*4096*256;
    #pragma unroll
    for (int r = ty; r < 32; r += 8)
        tile[r][tx] = src[(size_t)(f0+r)*256 + o0 + tx];
    __syncthreads();
    __half* dh = oh + (size_t)h2*256*4096;
    __half* dl = ol + (size_t)h2*256*4096;
    #pragma unroll
    for (int r = ty; r < 32; r += 8) {
        float v = tile[tx][r];
        __half hh = __float2half_rn(v);
        size_t o = (size_t)(o0+r)*4096 + f0 + tx;
        dh[o] = hh;
        dl[o] = __float2half_rn(v - __half2float(hh));
    }
}

// ---------------- xpos table build ----------------
__global__ void build_xt(float4* __restrict__ xt)
{
    int tt = blockIdx.x;
    int j  = threadIdx.x;
    float base = (2.f*j + 0.4f*256.f) / (1.4f*256.f);
    float scale = powf(base, (float)tt * (1.f/512.f));
    float invf  = powf(10000.f, -(float)j * (1.f/128.f));
    float s, c;
    sincosf((float)tt * invf, &s, &c);
    xt[tt*128 + j] = make_float4(c, s, scale, 1.f/scale);
}

// ---------------- fp16 mma GEMM, cp.async 2-stage, ldmatrix ----------------
// EPI: 0=fp32 C; 1=qkv xpos epilogue; 2=relu -> fp16 hi/lo; 3=fp32 C + hi/lo;
//      4=gated groupnorm+silu fused
// AFP32: A given as fp32. KS: K-split (blockIdx.y; requires M<=128).
// NT: CTA N-tile (128 or 64). NT=64 -> 3 CTAs/SM (reg cap 85).
#define SROW 40
#define ABYT (128*SROW*2)

template<int PASSES, int EPI, int AFP32, int KS, int NT>
__global__ __launch_bounds__(256, (NT == 64) ? 3 : 2)
void hgemm_ca(const float* __restrict__ Af,
              const __half* __restrict__ Ah, const __half* __restrict__ Al,
              const __half* __restrict__ Bh, const __half* __restrict__ Bl,
              float* __restrict__ C, float* __restrict__ Qo, float* __restrict__ Ko,
              float* __restrict__ Vo, const float4* __restrict__ xt,
              int K, int lda, int ldb, int ldc, size_t sA, size_t sB, size_t sC,
              size_t sKC)
{
    constexpr int JN = NT / 32;                       // j-tiles per warp (N dir)
    constexpr uint32_t BBYT = (uint32_t)NT * 80u;     // B array bytes per plane
    constexpr uint32_t BOFF = (PASSES == 3) ? 2u*ABYT : 1u*ABYT;   // B-hi offset
    constexpr uint32_t BLOFF = BOFF + BBYT;           // B-lo offset
    constexpr uint32_t STGB = BOFF + ((PASSES == 3) ? 2u*BBYT : BBYT);
    extern __shared__ char dsm[];
    uint32_t sbase = smem_u32(dsm);

    int t = threadIdx.x;
    int row0, koff = 0, Keff = K;
    if constexpr (KS > 1) {
        row0 = 0;
        Keff = K / KS;
        koff = (int)(blockIdx.y * Keff);
    } else {
        row0 = blockIdx.y << 7;
    }
    int col0 = blockIdx.x * NT;
    Bh += (size_t)blockIdx.z * sB;
    if constexpr (PASSES == 3) Bl += (size_t)blockIdx.z * sB;
    if constexpr (EPI == 0 || EPI == 3) {
        C += (size_t)blockIdx.z * sC;
        if constexpr (KS > 1) C += (size_t)blockIdx.y * sKC;
    }

    int wid = t >> 5, lane = t & 31;
    int warpM = (wid >> 2) * 64, warpN = (wid & 3) * (NT/4);
    int grp = lane >> 2, tig = lane & 3;

    int laneA = ((lane & 7) + ((lane >> 3) & 1)*8)*SROW + (lane >> 4)*8;
    int laneB = ((lane & 7) + (lane >> 4)*8)*SROW + ((lane >> 3) & 1)*8;

    int r0 = t >> 2, q0 = t & 3;
    uint32_t sm0 = (uint32_t)(r0*80 + q0*16);
    uint32_t sm1 = (uint32_t)((r0+64)*80 + q0*16);

    const __half *pA = nullptr, *pA2 = nullptr, *pAl = nullptr, *pAl2 = nullptr;
    const float *pf0 = nullptr, *pf1 = nullptr;
    if constexpr (AFP32) {
        pf0 = Af + (size_t)blockIdx.z * sA + (size_t)(row0 + r0)*lda + q0*8 + koff;
        pf1 = pf0 + (size_t)64*lda;
    } else {
        pA  = Ah + (size_t)blockIdx.z * sA + (size_t)(row0 + r0)*lda + q0*8 + koff;
        pA2 = pA + (size_t)64*lda;
        if constexpr (PASSES == 3) {
            pAl  = Al + (size_t)blockIdx.z * sA + (size_t)(row0 + r0)*lda + q0*8 + koff;
            pAl2 = pAl + (size_t)64*lda;
        }
    }
    const __half* pB  = Bh + (size_t)(col0 + r0)*ldb + q0*8 + koff;
    const __half* pB2 = (NT == 128) ? (pB + (size_t)64*ldb) : nullptr;
    const __half *pBl = nullptr, *pBl2 = nullptr;
    if constexpr (PASSES == 3) {
        pBl = Bl + (size_t)(col0 + r0)*ldb + q0*8 + koff;
        if constexpr (NT == 128) pBl2 = pBl + (size_t)64*ldb;
    }

    float4 fa0, fa1, fa2, fa3;

#define LDA_F(k0) do { \
    fa0 = *(const float4*)(pf0 + (k0));  fa1 = *(const float4*)(pf0 + (k0) + 4); \
    fa2 = *(const float4*)(pf1 + (k0));  fa3 = *(const float4*)(pf1 + (k0) + 4); } while(0)

#define STS_A(s) do { \
    char* sb_ = dsm + (size_t)(s)*STGB; \
    __half2 h0=__floats2half2_rn(fa0.x,fa0.y), h1=__floats2half2_rn(fa0.z,fa0.w); \
    __half2 h2=__floats2half2_rn(fa1.x,fa1.y), h3=__floats2half2_rn(fa1.z,fa1.w); \
    __half2 h4=__floats2half2_rn(fa2.x,fa2.y), h5=__floats2half2_rn(fa2.z,fa2.w); \
    __half2 h6=__floats2half2_rn(fa3.x,fa3.y), h7=__floats2half2_rn(fa3.z,fa3.w); \
    uint4 hv0, hv1; \
    hv0.x=*(uint32_t*)&h0; hv0.y=*(uint32_t*)&h1; hv0.z=*(uint32_t*)&h2; hv0.w=*(uint32_t*)&h3; \
    hv1.x=*(uint32_t*)&h4; hv1.y=*(uint32_t*)&h5; hv1.z=*(uint32_t*)&h6; hv1.w=*(uint32_t*)&h7; \
    *(uint4*)(sb_ + sm0) = hv0; *(uint4*)(sb_ + sm1) = hv1; \
    if constexpr (PASSES == 3) { \
        float2 f0=__half22float2(h0), f1=__half22float2(h1); \
        float2 f2=__half22float2(h2), f3=__half22float2(h3); \
        float2 f4=__half22float2(h4), f5=__half22float2(h5); \
        float2 f6=__half22float2(h6), f7=__half22float2(h7); \
        __half2 l0=__floats2half2_rn(fa0.x-f0.x, fa0.y-f0.y); \
        __half2 l1=__floats2half2_rn(fa0.z-f1.x, fa0.w-f1.y); \
        __half2 l2=__floats2half2_rn(fa1.x-f2.x, fa1.y-f2.y); \
        __half2 l3=__floats2half2_rn(fa1.z-f3.x, fa1.w-f3.y); \
        __half2 l4=__floats2half2_rn(fa2.x-f4.x, fa2.y-f4.y); \
        __half2 l5=__floats2half2_rn(fa2.z-f5.x, fa2.w-f5.y); \
        __half2 l6=__floats2half2_rn(fa3.x-f6.x, fa3.y-f6.y); \
        __half2 l7=__floats2half2_rn(fa3.z-f7.x, fa3.w-f7.y); \
        uint4 lv0, lv1; \
        lv0.x=*(uint32_t*)&l0; lv0.y=*(uint32_t*)&l1; lv0.z=*(uint32_t*)&l2; lv0.w=*(uint32_t*)&l3; \
        lv1.x=*(uint32_t*)&l4; lv1.y=*(uint32_t*)&l5; lv1.z=*(uint32_t*)&l6; lv1.w=*(uint32_t*)&l7; \
        *(uint4*)(sb_ + ABYT + sm0) = lv0; *(uint4*)(sb_ + ABYT + sm1) = lv1; \
    } } while(0)

#define LD_STAGE(s, k0) do { \
    uint32_t sb_ = sbase + (uint32_t)(s)*STGB; \
    if constexpr (!AFP32) { \
        cp16(sb_ + sm0, pA + (k0));  cp16(sb_ + sm1, pA2 + (k0)); \
        if constexpr (PASSES == 3) { \
            cp16(sb_ + ABYT + sm0, pAl + (k0)); cp16(sb_ + ABYT + sm1, pAl2 + (k0)); } } \
    cp16(sb_ + BOFF + sm0, pB + (k0)); \
    if constexpr (NT == 128) cp16(sb_ + BOFF + sm1, pB2 + (k0)); \
    if constexpr (PASSES == 3) { \
        cp16(sb_ + BLOFF + sm0, pBl + (k0)); \
        if constexpr (NT == 128) cp16(sb_ + BLOFF + sm1, pBl2 + (k0)); } \
    asm volatile("cp.async.commit_group;" ::: "memory"); } while(0)

    float acc[4][JN][4] = {};

    int nk = Keff >> 5;
    if constexpr (AFP32) { LDA_F(0); STS_A(0); }
    LD_STAGE(0, 0);
    for (int kc = 0; kc < nk; kc++) {
        bool more = (kc + 1 < nk);
        if (more) {
            if constexpr (AFP32) LDA_F((kc+1)*32);
            LD_STAGE((kc+1)&1, (kc+1)*32);
            asm volatile("cp.async.wait_group 1;" ::: "memory");
        } else {
            asm volatile("cp.async.wait_group 0;" ::: "memory");
        }
        __syncthreads();

        uint32_t st  = sbase + (uint32_t)(kc & 1)*STGB;
        uint32_t aAh = st + (uint32_t)(2*(warpM*SROW + laneA));
        uint32_t aBh = st + BOFF + (uint32_t)(2*(warpN*SROW + laneB));

        #pragma unroll
        for (int ksb = 0; ksb < 64; ksb += 32) {
            uint32_t bh[2*JN];
            #pragma unroll
            for (int u = 0; u < JN/2; u++)
                ldsm4(bh[4*u], bh[4*u+1], bh[4*u+2], bh[4*u+3],
                      aBh + u*16*SROW*2 + ksb);
            uint32_t a[4][4];
            #pragma unroll
            for (int i = 0; i < 4; i++)
                ldsm4(a[i][0], a[i][1], a[i][2], a[i][3], aAh + i*16*SROW*2 + ksb);

            if constexpr (PASSES == 3) {
                uint32_t bl[2*JN];
                #pragma unroll
                for (int u = 0; u < JN/2; u++)
                    ldsm4(bl[4*u], bl[4*u+1], bl[4*u+2], bl[4*u+3],
                          aBh + BBYT + u*16*SROW*2 + ksb);
                #pragma unroll
                for (int i = 0; i < 4; i++)
                    #pragma unroll
                    for (int j = 0; j < JN; j++)
                        mma_f16(acc[i][j], a[i], &bh[2*j]);
                #pragma unroll
                for (int i = 0; i < 4; i++)
                    #pragma unroll
                    for (int j = 0; j < JN; j++)
                        mma_f16(acc[i][j], a[i], &bl[2*j]);
                #pragma unroll
                for (int i = 0; i < 4; i++)
                    ldsm4(a[i][0], a[i][1], a[i][2], a[i][3], aAh + ABYT + i*16*SROW*2 + ksb);
                #pragma unroll
                for (int i = 0; i < 4; i++)
                    #pragma unroll
                    for (int j = 0; j < JN; j++)
                        mma_f16(acc[i][j], a[i], &bh[2*j]);
            } else {
                #pragma unroll
                for (int i = 0; i < 4; i++)
                    #pragma unroll
                    for (int j = 0; j < JN; j++)
                        mma_f16(acc[i][j], a[i], &bh[2*j]);
            }
        }
        __syncthreads();
        if constexpr (AFP32) { if (more) STS_A((kc+1)&1); }
    }
#undef LD_STAGE
#undef STS_A
#undef LDA_F

    if constexpr (EPI == 0) {
        #pragma unroll
        for (int i = 0; i < 4; i++) {
            int r = row0 + warpM + i*16 + grp;
            #pragma unroll
            for (int j = 0; j < JN; j++) {
                float* cp = C + (size_t)r*ldc + col0 + warpN + j*8 + tig*2;
                *(float2*)cp = make_float2(acc[i][j][0], acc[i][j][1]);
                *(float2*)(cp + (size_t)8*ldc) = make_float2(acc[i][j][2], acc[i][j][3]);
            }
        }
    } else if constexpr (EPI == 1) {
        #pragma unroll
        for (int i = 0; i < 4; i++) {
            int rA = row0 + warpM + i*16 + grp;
            #pragma unroll
            for (int j = 0; j < JN; j++) {
                int c0 = col0 + warpN + j*8 + tig*2;
                #pragma unroll
                for (int half = 0; half < 2; half++) {
                    int row = rA + half*8;
                    float v0 = acc[i][j][half*2], v1 = acc[i][j][half*2+1];
                    int b = row >> 10, tt = row & 1023;
                    if (c0 < 512) {
                        int cc = c0 & 255;
                        float4 e = xt[tt*128 + (cc >> 1)];
                        float sc = (c0 < 256) ? e.z : e.w;
                        float cs = e.x*sc, ss = e.y*sc;
                        float o0 = v0*cs - v1*ss;
                        float o1 = v1*cs + v0*ss;
                        float* dst = ((c0 < 256) ? Qo : Ko) +
                            (((((size_t)b*16 + (cc>>4))*1024 + tt)<<4) + (cc & 15));
                        *(float2*)dst = make_float2(o0, o1);
                    } else {
                        int e2 = c0 - 512;
                        float* dst = Vo +
                            (((((size_t)b*16 + (e2>>4))*1024 + tt)<<4) + (e2 & 15));
                        *(float2*)dst = make_float2(v0, v1);
                    }
                }
            }
        }
    } else if constexpr (EPI == 4) {
        __half* Gp = (__half*)Qo;
        const __half* Rh = (const __half*)Ko;
        const __half* Rl = (const __half*)Vo;
        #pragma unroll
        for (int i = 0; i < 4; i++) {
            #pragma unroll
            for (int half = 0; half < 2; half++) {
                int rr = row0 + warpM + i*16 + grp + half*8;
                int b = rr >> 10, tt = rr & 1023;
                #pragma unroll
                for (int jp = 0; jp < JN; jp += 2) {
                    int hcol = col0 + warpN + jp*8;
                    int h = hcol >> 4;
                    size_t rbase = (((size_t)b*16 + h)*1024 + tt)*16 + tig*2;
                    __half2 ah = *(const __half2*)(Rh + rbase);
                    __half2 al = *(const __half2*)(Rl + rbase);
                    __half2 bh2 = *(const __half2*)(Rh + rbase + 8);
                    __half2 bl2 = *(const __half2*)(Rl + rbase + 8);
                    float2 f0 = __half22float2(ah),  f0l = __half22float2(al);
                    float2 f1 = __half22float2(bh2), f1l = __half22float2(bl2);
                    float rv0 = f0.x + f0l.x, rv1 = f0.y + f0l.y;
                    float rv2 = f1.x + f1l.x, rv3 = f1.y + f1l.y;
                    float s  = rv0 + rv1 + rv2 + rv3;
                    float s2 = rv0*rv0 + rv1*rv1 + rv2*rv2 + rv3*rv3;
                    s  += __shfl_xor_sync(0xffffffffu, s, 1);
                    s  += __shfl_xor_sync(0xffffffffu, s, 2);
                    s2 += __shfl_xor_sync(0xffffffffu, s2, 1);
                    s2 += __shfl_xor_sync(0xffffffffu, s2, 2);
                    float m = s * (1.f/16.f);
                    float var = s2 * (1.f/16.f) - m*m;
                    float rstd = rsqrtf(var + 1e-5f);
                    float g0 = acc[i][jp][half*2],   g1 = acc[i][jp][half*2+1];
                    float g2 = acc[i][jp+1][half*2], g3 = acc[i][jp+1][half*2+1];
                    float o0 = g0/(1.f+__expf(-g0)) * ((rv0 - m)*rstd);
                    float o1 = g1/(1.f+__expf(-g1)) * ((rv1 - m)*rstd);
                    float o2 = g2/(1.f+__expf(-g2)) * ((rv2 - m)*rstd);
                    float o3 = g3/(1.f+__expf(-g3)) * ((rv3 - m)*rstd);
                    __half* dst = Gp + (size_t)rr*256 + h*16 + tig*2;
                    *(__half2*)dst       = __floats2half2_rn(o0, o1);
                    *(__half2*)(dst + 8) = __floats2half2_rn(o2, o3);
                }
            }
        }
    } else {
        __half* Hp = (__half*)Qo + (size_t)blockIdx.z * sC;
        __half* Lp = (__half*)Ko + (size_t)blockIdx.z * sC;
        #pragma unroll
        for (int i = 0; i < 4; i++) {
            int r = row0 + warpM + i*16 + grp;
            #pragma unroll
            for (int j = 0; j < JN; j++) {
                int cb = col0 + warpN + j*8 + tig*2;
                #pragma unroll
                for (int half = 0; half < 2; half++) {
                    int rr = r + half*8;
                    float v0 = acc[i][j][half*2], v1 = acc[i][j][half*2+1];
                    if constexpr (EPI == 2) { v0 = fmaxf(v0, 0.f); v1 = fmaxf(v1, 0.f); }
                    if constexpr (EPI == 3) {
                        *(float2*)(C + (size_t)rr*ldc + cb) = make_float2(v0, v1);
                    }
                    __half2 hh = __floats2half2_rn(v0, v1);
                    float2 fh = __half22float2(hh);
                    __half2 ll = __floats2half2_rn(v0 - fh.x, v1 - fh.y);
                    *(__half2*)(Hp + (size_t)rr*ldc + cb) = hh;
                    *(__half2*)(Lp + (size_t)rr*ldc + cb) = ll;
                }
            }
        }
    }
}

// ---------------- split-K finalize: r ----------
__global__ void rfin(const float* __restrict__ part, __half* __restrict__ rh,
                     __half* __restrict__ rl)
{
    int i = blockIdx.x*256 + threadIdx.x;
    float s = part[i] + part[i + 524288] + part[i + 2*524288] + part[i + 3*524288];
    s = fmaxf(s, 0.f);
    int h2 = i >> 15, rr = (i >> 8) & 127, f = i & 255;
    size_t o = (size_t)rr*4096 + h2*256 + f;
    __half hh = __float2half_rn(s);
    rh[o] = hh;
    rl[o] = __float2half_rn(s - __half2float(hh));
}

// ---------------- split-K finalize: temp8 (also seeds GRU state pgA) -------
__global__ void tfin(const float* __restrict__ part, float* __restrict__ t8,
                     __half* __restrict__ th, __half* __restrict__ tl,
                     float* __restrict__ pgA)
{
    int i = blockIdx.x*256 + threadIdx.x;
    float s = 0.f;
    #pragma unroll
    for (int k2 = 0; k2 < 8; k2++) s += part[i + k2*65536];
    t8[i] = s;
    if (i < 4096) pgA[i] = s;
    __half hh = __float2half_rn(s);
    th[i] = hh;
    tl[i] = __float2half_rn(s - __half2float(hh));
}

// ---------------- retention scan v3 ----------------
__global__ __launch_bounds__(256)
void retention_kernel(const float* __restrict__ Q, const float* __restrict__ K,
                      const float* __restrict__ V,
                      __half* __restrict__ Oh, __half* __restrict__ Ol,
                      float* __restrict__ kv_out)
{
    __shared__ float ks[64][20], vs[64][20];
    __shared__ float kvs[16][20];
    __shared__ float pw[65];

    int bh = blockIdx.x;
    int h = bh & 15;
    int tid = threadIdx.x;
    int lane = tid & 31;
    int c = tid >> 2, part = tid & 3;
    int cmax = c | 7;
    float gamma = 1.f - exp2f(-5.f - (float)h);
    float inv_g = 1.f / gamma;
    if (tid < 65) pw[tid] = powf(gamma, (float)tid);
    if (tid < 64)
        *(float4*)&kvs[tid >> 2][(tid & 3)*4] = make_float4(0.f, 0.f, 0.f, 0.f);
    __syncthreads();
    float w0c = pw[c];
    float cf  = pw[c+1];
    float w63 = pw[63];

    size_t base = (size_t)bh * T_ * DH;

    for (int ch = 0; ch < NCHUNK; ch++) {
        size_t cb = base + (size_t)ch * CCH * DH;
        float4 qv  = *(const float4*)(Q + cb + (size_t)tid*4);
        float4 kv4 = *(const float4*)(K + cb + (size_t)tid*4);
        float4 vv4 = *(const float4*)(V + cb + (size_t)tid*4);
        qv.x *= 0.25f; qv.y *= 0.25f; qv.z *= 0.25f; qv.w *= 0.25f;
        __syncthreads();
        *(float4*)&ks[c][part*4] = kv4;
        *(float4*)&vs[c][part*4] = vv4;
        __syncthreads();

        float a0 = 0.f, a1 = 0.f, a2 = 0.f, a3 = 0.f;
        float w = w0c;
        #pragma unroll 4
        for (int e = 0; e <= cmax; e++) {
            float4 ke = *(const float4*)&ks[e][part*4];
            float r = qv.x*ke.x;
            r = fmaf(qv.y, ke.y, r);
            r = fmaf(qv.z, ke.z, r);
            r = fmaf(qv.w, ke.w, r);
            r += __shfl_xor_sync(0xffffffffu, r, 1);
            r += __shfl_xor_sync(0xffffffffu, r, 2);
            r *= (e <= c) ? w : 0.f;
            w *= inv_g;
            float4 ve = *(const float4*)&vs[e][part*4];
            a0 = fmaf(r, ve.x, a0);
            a1 = fmaf(r, ve.y, a1);
            a2 = fmaf(r, ve.z, a2);
            a3 = fmaf(r, ve.w, a3);
        }
        float x0 = 0.f, x1 = 0.f, x2 = 0.f, x3 = 0.f;
        float qarr[4] = {qv.x, qv.y, qv.z, qv.w};
        #pragma unroll
        for (int d = 0; d < 16; d++) {
            int src = (lane & 28) | (d >> 2);
            float qd = __shfl_sync(0xffffffffu, qarr[d & 3], src);
            float4 kd = *(const float4*)&kvs[d][part*4];
            x0 = fmaf(qd, kd.x, x0);
            x1 = fmaf(qd, kd.y, x1);
            x2 = fmaf(qd, kd.z, x2);
            x3 = fmaf(qd, kd.w, x3);
        }
        float o0 = fmaf(x0, cf, a0);
        float o1 = fmaf(x1, cf, a1);
        float o2 = fmaf(x2, cf, a2);
        float o3 = fmaf(x3, cf, a3);

        size_t oo = cb + (size_t)tid*4;
        __half2 h01 = __floats2half2_rn(o0, o1);
        __half2 h23 = __floats2half2_rn(o2, o3);
        float2 f01 = __half22float2(h01), f23 = __half22float2(h23);
        __half2 l01 = __floats2half2_rn(o0 - f01.x, o1 - f01.y);
        __half2 l23 = __floats2half2_rn(o2 - f23.x, o3 - f23.y);
        *(__half2*)(Oh + oo)     = h01;
        *(__half2*)(Oh + oo + 2) = h23;
        *(__half2*)(Ol + oo)     = l01;
        *(__half2*)(Ol + oo + 2) = l23;

        __syncthreads();
        if (tid < 64) {
            int d = tid >> 2, q4 = (tid & 3)*4;
            float4 nv = *(const float4*)&kvs[d][q4];
            float g64 = w63 * gamma;
            nv.x *= g64; nv.y *= g64; nv.z *= g64; nv.w *= g64;
            float w2 = w63;
            #pragma unroll 4
            for (int cc = 0; cc < 64; cc++) {
                float kwv = ks[cc][d] * w2;
                w2 *= inv_g;
                float4 vc = *(const float4*)&vs[cc][q4];
                nv.x = fmaf(kwv, vc.x, nv.x);
                nv.y = fmaf(kwv, vc.y, nv.y);
                nv.z = fmaf(kwv, vc.z, nv.z);
                nv.w = fmaf(kwv, vc.w, nv.w);
            }
            *(float4*)&kvs[d][q4] = nv;
        }
    }
    __syncthreads();
    if (kv_out) kv_out[(size_t)bh*256 + tid] = kvs[tid >> 4][tid & 15];
}

// ---------------- wa[h][f] = dot(W_gat[h][f,:], a2[h]) ----------------
__global__ void wa_kernel(const float* __restrict__ Wgat, const float* __restrict__ agat,
                          float* __restrict__ wa)
{
    int gw = blockIdx.x*8 + (threadIdx.x >> 5);
    int lane = threadIdx.x & 31;
    int h2 = gw >> 12, f = gw & 4095;
    const float* w = Wgat + (size_t)h2*4096*256 + (size_t)f*256;
    const float* a2 = agat + h2*512 + 256;
    float s = 0.f;
    #pragma unroll
    for (int c = lane; c < 256; c += 32) s = fmaf(w[c], a2[c], s);
    #pragma unroll
    for (int o = 16; o > 0; o >>= 1) s += __shfl_down_sync(0xffffffffu, s, o);
    if (lane == 0) wa[gw] = s;
}

// ---------------- merged s2 + softmax + z (fp16 hi/lo out) ----------------
__global__ __launch_bounds__(256)
void s2z_all(const float* __restrict__ gp_all, const float* __restrict__ wa,
             __half* __restrict__ zh, __half* __restrict__ zl)
{
    int b2 = blockIdx.x, ch = blockIdx.y;
    const float* gin = gp_all + (size_t)ch*1048576 + (size_t)b2*131072;
    __shared__ float pan[32][129];
    __shared__ float swa[16][129];
    __shared__ float s2m[16][33];
    __shared__ float att[16][33];
    int t = threadIdx.x;
    int m = t & 31, hg = t >> 5;
    float a0 = 0.f, a1 = 0.f;

    for (int fp = 0; fp < 4096; fp += 128) {
        __syncthreads();
        #pragma unroll
        for (int s = 0; s < 16; s++) {
            int idx = t + s*256;
            pan[idx >> 7][idx & 127] = gin[(size_t)(idx >> 7)*4096 + fp + (idx & 127)];
        }
        #pragma unroll
        for (int s = 0; s < 8; s++) {
            int idx = t + s*256;
            swa[idx >> 7][idx & 127] = wa[(size_t)(idx >> 7)*4096 + fp + (idx & 127)];
        }
        __syncthreads();
        #pragma unroll 8
        for (int ff = 0; ff < 128; ff++) {
            float g = pan[m][ff];
            a0 = fmaf(g, swa[hg][ff], a0);
            a1 = fmaf(g, swa[hg+8][ff], a1);
        }
    }
    s2m[hg][m] = a0;
    s2m[hg+8][m] = a1;
    __syncthreads();
    if (t < 16) {
        float mx = -1e30f;
        #pragma unroll
        for (int i = 0; i < 32; i++) mx = fmaxf(mx, s2m[t][i]);
        float sum = 0.f;
        #pragma unroll
        for (int i = 0; i < 32; i++) { float e = __expf(s2m[t][i]-mx); att[t][i] = e; sum += e; }
        float inv = 1.f/sum;
        #pragma unroll
        for (int i = 0; i < 32; i++) att[t][i] *= inv;
    }
    __syncthreads();

    int h2 = t >> 4, fl = t & 15;
    size_t zb = ((((size_t)ch*8 + b2)*16) + h2)*4096;
    __half* zdh = zh + zb;
    __half* zdl = zl + zb;
    for (int fp = 0; fp < 4096; fp += 128) {
        __syncthreads();
        #pragma unroll
        for (int s = 0; s < 16; s++) {
            int idx = t + s*256;
            pan[idx >> 7][idx & 127] = gin[(size_t)(idx >> 7)*4096 + fp + (idx & 127)];
        }
        __syncthreads();
        #pragma unroll
        for (int ii = 0; ii < 8; ii++) {
            int ff = ii*16 + fl;
            float a = 0.f;
            #pragma unroll
            for (int mm = 0; mm < 32; mm++) a = fmaf(att[h2][mm], pan[mm][ff], a);
            __half hh = __float2half_rn(a);
            zdh[fp + ff] = hh;
            zdl[fp + ff] = __float2half_rn(a - __half2float(hh));
        }
    }
}

// ---------------- fused GRU step ----------------
__global__ __launch_bounds__(256)
void gru_step(const float* __restrict__ gi_ch, const float* __restrict__ prev,
              const float* __restrict__ whh, const float* __restrict__ b_ih,
              const float* __restrict__ b_hh, float* __restrict__ cur)
{
    int gw = blockIdx.x*8 + (threadIdx.x >> 5);
    int lane = threadIdx.x & 31;
    int b2 = gw >> 9, c = gw & 511;
    const float* x  = prev + b2*512;
    const float* w0 = whh + (size_t)c*512;
    float s0 = 0.f, s1 = 0.f, s2 = 0.f;
    #pragma unroll 4
    for (int f = lane; f < 512; f += 32) {
        float xv = x[f];
        s0 = fmaf(xv, w0[f], s0);
        s1 = fmaf(xv, w0[f + 512*512], s1);
        s2 = fmaf(xv, w0[f + 1024*512], s2);
    }
    #pragma unroll
    for (int o = 16; o > 0; o >>= 1) {
        s0 += __shfl_down_sync(0xffffffffu, s0, o);
        s1 += __shfl_down_sync(0xffffffffu, s1, o);
        s2 += __shfl_down_sync(0xffffffffu, s2, o);
    }
    if (lane == 0) {
        float ir = gi_ch[b2*1536 + c]        + b_ih[c];
        float iz = gi_ch[b2*1536 + c + 512]  + b_ih[c + 512];
        float in_= gi_ch[b2*1536 + c + 1024] + b_ih[c + 1024];
        float hr = s0 + b_hh[c];
        float hz = s1 + b_hh[c + 512];
        float hn = s2 + b_hh[c + 1024];
        float rg = 1.f/(1.f + __expf(-(ir + hr)));
        float zg = 1.f/(1.f + __expf(-(iz + hz)));
        float ng = tanhf(in_ + rg*hn);
        cur[b2*512 + c] = (1.f - zg)*ng + zg*prev[b2*512 + c];
    }
}

__global__ void expand_pg(const float* __restrict__ pg8, float* __restrict__ dst)
{
    int idx = blockIdx.x*256 + threadIdx.x;
    int row = idx >> 9;
    dst[idx] = pg8[(row >> 5)*512 + (idx & 511)];
}

// ---------------- orchestration ----------------
extern "C" void kernel_launch(void* const* d_in, const int* in_sizes, int n_in,
                              void* d_out, int out_size)
{
    const float* hs   = (const float*)d_in[0];
    const float* Wqkv = (const float*)d_in[1];
    const float* Wg   = (const float*)d_in[2];
    const float* Wp   = (const float*)d_in[3];
    const float* Wgp  = (const float*)d_in[4];
    const float* Wgl  = (const float*)d_in[5];
    const float* Wgat = (const float*)d_in[6];
    const float* agat = (const float*)d_in[7];
    const float* wih  = (const float*)d_in[8];
    const float* whh  = (const float*)d_in[9];
    const float* bih  = (const float*)d_in[10];
    const float* bhh  = (const float*)d_in[11];
    float* out = (float*)d_out;

    float *q, *k, *v, *gp, *t8, *wa, *pgA, *pgB, *giall, *rpart, *tpart;
    float4* xt;
    __half *reth, *retl, *tmph, *wqkvh, *wqkvl, *wgh, *wph, *wgph, *wgpl;
    __half *zh, *zl, *rh, *rl, *t8h, *t8l, *wgath, *wgatl, *wglh, *wgll, *wihh, *wihl;
    cudaGetSymbolAddress((void**)&q,   g_q);
    cudaGetSymbolAddress((void**)&k,   g_k);
    cudaGetSymbolAddress((void**)&v,   g_v);
    cudaGetSymbolAddress((void**)&gp,  g_gp);
    cudaGetSymbolAddress((void**)&t8,  g_temp8);
    cudaGetSymbolAddress((void**)&wa,  g_wa);
    cudaGetSymbolAddress((void**)&pgA, g_pg8a);
    cudaGetSymbolAddress((void**)&pgB, g_pg8b);
    cudaGetSymbolAddress((void**)&giall, g_giall);
    cudaGetSymbolAddress((void**)&rpart, g_rpart);
    cudaGetSymbolAddress((void**)&tpart, g_tpart);
    cudaGetSymbolAddress((void**)&xt,  g_xt);
    cudaGetSymbolAddress((void**)&reth, g_reth);
    cudaGetSymbolAddress((void**)&retl, g_retl);
    cudaGetSymbolAddress((void**)&tmph, g_tmph);
    cudaGetSymbolAddress((void**)&wqkvh, g_wqkvh);
    cudaGetSymbolAddress((void**)&wqkvl, g_wqkvl);
    cudaGetSymbolAddress((void**)&wgh, g_wgh);
    cudaGetSymbolAddress((void**)&wph, g_wph);
    cudaGetSymbolAddress((void**)&wgph, g_wgph);
    cudaGetSymbolAddress((void**)&wgpl, g_wgpl);
    cudaGetSymbolAddress((void**)&zh, g_zh);
    cudaGetSymbolAddress((void**)&zl, g_zl);
    cudaGetSymbolAddress((void**)&rh, g_rh);
    cudaGetSymbolAddress((void**)&rl, g_rl);
    cudaGetSymbolAddress((void**)&t8h, g_t8h);
    cudaGetSymbolAddress((void**)&t8l, g_t8l);
    cudaGetSymbolAddress((void**)&wgath, g_wgath);
    cudaGetSymbolAddress((void**)&wgatl, g_wgatl);
    cudaGetSymbolAddress((void**)&wglh, g_wglh);
    cudaGetSymbolAddress((void**)&wgll, g_wgll);
    cudaGetSymbolAddress((void**)&wihh, g_wihh);
    cudaGetSymbolAddress((void**)&wihl, g_wihl);

    cudaFuncSetAttribute((const void*)hgemm_ca<3,1,1,1,64>,  cudaFuncAttributeMaxDynamicSharedMemorySize, 61440);
    cudaFuncSetAttribute((const void*)hgemm_ca<1,4,1,1,128>, cudaFuncAttributeMaxDynamicSharedMemorySize, 40960);
    cudaFuncSetAttribute((const void*)hgemm_ca<1,0,0,1,128>, cudaFuncAttributeMaxDynamicSharedMemorySize, 40960);
    cudaFuncSetAttribute((const void*)hgemm_ca<3,0,0,1,128>, cudaFuncAttributeMaxDynamicSharedMemorySize, 81920);
    cudaFuncSetAttribute((const void*)hgemm_ca<3,0,0,4,128>, cudaFuncAttributeMaxDynamicSharedMemorySize, 81920);
    cudaFuncSetAttribute((const void*)hgemm_ca<3,0,0,8,128>, cudaFuncAttributeMaxDynamicSharedMemorySize, 81920);

    bool full = (out_size >= OUT1_N + KV_N + PG_N);
    float* kvdst = full ? (out + OUT1_N) : nullptr;
    float* pgdst = full ? (out + OUT1_N + KV_N) : nullptr;

    static cudaStream_t sConv = nullptr;
    static cudaEvent_t evTop = nullptr, evConv = nullptr;
    if (sConv == nullptr) {
        cudaStreamCreateWithFlags(&sConv, cudaStreamNonBlocking);
        cudaEventCreateWithFlags(&evTop,  cudaEventDisableTiming);
        cudaEventCreateWithFlags(&evConv, cudaEventDisableTiming);
    }

    // ---- main stream: qkv prerequisites ----
    split_hl_h<<<192, 256>>>(Wqkv, wqkvh, wqkvl, 196608);
    build_xt<<<1024, 128>>>(xt);

    // ---- fork: weight conversions overlap the HMMA-bound qkv GEMM ----
    cudaEventRecord(evTop, 0);
    cudaStreamWaitEvent(sConv, evTop, 0);
    split_hl_h<<<256, 256, 0, sConv>>>(Wgp, wgph, wgpl, 262144);
    conv2_h<<<128, 256, 0, sConv>>>(Wg, wgh, Wp, wph);
    tsplit_wgat<<<dim3(128, 8, 16), dim3(32, 8), 0, sConv>>>(Wgat, wgath, wgatl);
    split_hl_h<<<2048, 256, 0, sConv>>>(Wgl, wglh, wgll, 2097152);
    split_hl_h<<<768, 256, 0, sConv>>>(wih, wihh, wihl, 786432);
    wa_kernel<<<8192, 256, 0, sConv>>>(Wgat, agat, wa);
    cudaEventRecord(evConv, sConv);

    // ---- main stream: qkv GEMM (NT=64, 3 CTAs/SM) + retention ----
    hgemm_ca<3,1,1,1,64><<<dim3(12, 2048), 256, 61440>>>(hs, nullptr, nullptr,
        wqkvh, wqkvl, nullptr, q, k, v, xt, 256, 256, 256, 0, 0, 0, 0, 0);
    retention_kernel<<<B_*NH, 256>>>(q, k, v, reth, retl, kvdst);

    // ---- join conversions, then serial chain ----
    cudaStreamWaitEvent(0, evConv, 0);

    // gated GEMM with fused groupnorm+silu epilogue -> tmph
    hgemm_ca<1,4,1,1,128><<<dim3(2, 2048), 256, 40960>>>(hs, nullptr, nullptr,
        wgh, nullptr, nullptr, (float*)tmph, (float*)reth, (float*)retl, nullptr,
        256, 256, 256, 256, 0, 0, 0, 0);

    // out = normed_gated @ Wp^T
    hgemm_ca<1,0,0,1,128><<<dim3(2, 2048), 256, 40960>>>(nullptr, tmph, nullptr,
        wph, nullptr, out, nullptr, nullptr, nullptr, nullptr, 256, 256, 256, 256, 0, 0, 0, 0);

    // gat_proj (fp16 3-pass, z-batched over 16 chunks)
    hgemm_ca<3,0,0,1,128><<<dim3(2, 32, 16), 256, 81920>>>(nullptr, reth, retl,
        wgph, wgpl, gp, nullptr, nullptr, nullptr, nullptr, 1024, T_*DH, 1024, 256,
        (size_t)CCH*DH, 0, (size_t)4096*256, 0);

    // GAT attention -> z in fp16 hi/lo
    s2z_all<<<dim3(8, 16), 256>>>(gp, wa, zh, zl);

    // r partials: split-K 4 over K=4096, batched over h2
    hgemm_ca<3,0,0,4,128><<<dim3(2, 4, 16), 256, 81920>>>(nullptr, zh, zl,
        wgath, wgatl, rpart, nullptr, nullptr, nullptr, nullptr,
        4096, 16*4096, 4096, 256, 4096, (size_t)256*4096,
        (size_t)128*256, (size_t)16*128*256);
    rfin<<<2048, 256>>>(rpart, rh, rl);

    // temp8 partials: split-K 8 over K=4096
    hgemm_ca<3,0,0,8,128><<<dim3(4, 8, 1), 256, 81920>>>(nullptr, rh, rl,
        wglh, wgll, tpart, nullptr, nullptr, nullptr, nullptr,
        4096, 4096, 4096, 512, 0, 0, 0, (size_t)128*512);
    tfin<<<256, 256>>>(tpart, t8, t8h, t8l, pgA);

    // gi_all = t8 @ wih^T
    hgemm_ca<3,0,0,1,128><<<dim3(12, 1, 1), 256, 81920>>>(nullptr, t8h, t8l,
        wihh, wihl, giall, nullptr, nullptr, nullptr, nullptr,
        512, 512, 512, 1536, 0, 0, 0, 0);

    // GRU: 15 serial fused steps (pgA seeded by tfin)
    float *src = pgA, *dst = pgB;
    for (int ch = 1; ch < NCHUNK; ch++) {
        gru_step<<<512, 256>>>(giall + (size_t)ch*8*1536, src, whh, bih, bhh, dst);
        float* sw = src; src = dst; dst = sw;
    }

    // expand past_gat
    if (pgdst) expand_pg<<<512, 256>>>(src, pgdst);
}